// round 14
// baseline (speedup 1.0000x reference)
#include <cuda_runtime.h>
#include <cuda_fp16.h>

#define SB 2
#define SX 160
#define SY 192
#define SZ 160
#define WIN 21
#define HALF 10
#define NF 9830400ull          // SB*SX*SY*SZ
#define YP (SY / 2)            // 96
#define YSEG 3
#define YL (SY / YSEG)         // 64
#define XSEG 4
#define XLEN (SX / XSEG)       // 40
#define NPART (SB * YP * XSEG) // 768
#define LPAD (SZ + 2 * HALF)   // 180
#define S1N (SZ + 18)
#define RDEP 12
#define NBLK_AB (SB * SX * YSEG)   // 960
#define NITEMS (NBLK_AB + NPART)   // 1728
#define GRID 888                   // 148 SMs * 6 CTAs
#define NSEGC (SB * YSEG)          // 6 per-(b,seg) counters

// 4 channels packed as half2 (lane = y parity): x=(I), y=(J), z=(I2), w=(J2)
struct __align__(16) HQ { __half2 x, y, z, w; };

__device__ HQ g_q2[NF / 2];
__device__ __half2 g_e2[NF / 2];
__device__ HQ g_rq[(size_t)NBLK_AB * RDEP * SZ];
__device__ __half2 g_re[(size_t)NBLK_AB * RDEP * SZ];
__device__ double g_part[NPART];
__device__ int g_count;
__device__ int g_segc[NSEGC];

__global__ __launch_bounds__(SZ, 6) void mega(const float* __restrict__ I,
                                              const float* __restrict__ J,
                                              float* __restrict__ out) {
    __shared__ HQ      lQ[2][LPAD];
    __shared__ __half2 lE[2][LPAD];
    __shared__ HQ      s1Q[2][S1N];
    __shared__ __half2 s1E[2][S1N];
    __shared__ float   wsum[SZ / 32];
    __shared__ int     isLast;
    __shared__ double  shd[256];

    const int z = threadIdx.x;
    const __half2 zero2 = __floats2half2_rn(0.f, 0.f);
    const __half zeroh = __float2half(0.f);

    for (int item = blockIdx.x; item < NITEMS; item += GRID) {
        if (item < NBLK_AB) {
            // ================= passAB tile =================
            const int seg = item % YSEG;
            int t = item / YSEG;
            const int x = t % SX;
            const int b = t / SX;

            if (z < HALF) {
                HQ z4; z4.x = zero2; z4.y = zero2; z4.z = zero2; z4.w = zero2;
#pragma unroll
                for (int p = 0; p < 2; p++) {
                    lQ[p][z] = z4; lQ[p][SZ + HALF + z] = z4;
                    lE[p][z] = zero2; lE[p][SZ + HALF + z] = zero2;
                }
            }

            const int y0 = seg * YL;
            const int y1 = y0 + YL;
            const int ystart = (y0 - HALF > 0) ? (y0 - HALF) : 0;  // even
            const size_t planeBase = ((size_t)(b * SX + x)) * SY * SZ;
            const size_t ringBase = (size_t)item * RDEP;

            __half c0 = zeroh, c1 = zeroh, c2 = zeroh, c3 = zeroh, c4 = zeroh;

            float pi[4], pj[4];
#pragma unroll
            for (int l = 0; l < 4; l++) {
                pi[l] = 0.f; pj[l] = 0.f;
                const int yy = ystart + l;
                if (yy < SY) {
                    size_t o = planeBase + (size_t)yy * SZ + z;
                    pi[l] = I[o]; pj[l] = J[o];
                }
            }

            __syncthreads();

            for (int y = ystart; y < y1 + HALF; y += 4) {
                const int ip = (y - ystart) >> 1;

                // ring prefetch: pairs ip-11, ip-10, ip-9
                HQ hA, hM, hB; __half2 eA_, eM_, eB_;
                hA.x = zero2; hA.y = zero2; hA.z = zero2; hA.w = zero2; eA_ = zero2;
                hM = hA; eM_ = zero2; hB = hA; eB_ = zero2;
                if (ip >= 11) {
                    size_t r = (ringBase + (ip - 11) % RDEP) * SZ + z;
                    hA = g_rq[r]; eA_ = g_re[r];
                }
                if (ip >= 10) {
                    size_t r = (ringBase + (ip - 10) % RDEP) * SZ + z;
                    hM = g_rq[r]; eM_ = g_re[r];
                }
                if (ip >= 9) {
                    size_t r = (ringBase + (ip - 9) % RDEP) * SZ + z;
                    hB = g_rq[r]; eB_ = g_re[r];
                }

                // phase 0: stage products of both pairs
#pragma unroll
                for (int p = 0; p < 2; p++) {
                    HQ h;
                    h.x = __floats2half2_rn(pi[2 * p], pi[2 * p + 1]);
                    h.y = __floats2half2_rn(pj[2 * p], pj[2 * p + 1]);
                    h.z = __hmul2(h.x, h.x);
                    h.w = __hmul2(h.y, h.y);
                    lQ[p][HALF + z] = h;
                    lE[p][HALF + z] = __hmul2(h.x, h.y);
                }

                // prefetch next 4 lines
#pragma unroll
                for (int l = 0; l < 4; l++) {
                    pi[l] = 0.f; pj[l] = 0.f;
                    const int yn = y + 4 + l;
                    if (yn < SY) {
                        size_t o = planeBase + (size_t)yn * SZ + z;
                        pi[l] = I[o]; pj[l] = J[o];
                    }
                }
                __syncthreads();

                // phase 1: 3-tap stage
#pragma unroll
                for (int p = 0; p < 2; p++) {
                    {
                        const int i = z;
                        HQ a0 = lQ[p][i], a1 = lQ[p][i + 1], a2 = lQ[p][i + 2];
                        HQ r;
                        r.x = __hadd2(__hadd2(a0.x, a1.x), a2.x);
                        r.y = __hadd2(__hadd2(a0.y, a1.y), a2.y);
                        r.z = __hadd2(__hadd2(a0.z, a1.z), a2.z);
                        r.w = __hadd2(__hadd2(a0.w, a1.w), a2.w);
                        s1Q[p][i] = r;
                        s1E[p][i] = __hadd2(__hadd2(lE[p][i], lE[p][i + 1]), lE[p][i + 2]);
                    }
                    if (z < S1N - SZ) {
                        const int i = SZ + z;
                        HQ a0 = lQ[p][i], a1 = lQ[p][i + 1], a2 = lQ[p][i + 2];
                        HQ r;
                        r.x = __hadd2(__hadd2(a0.x, a1.x), a2.x);
                        r.y = __hadd2(__hadd2(a0.y, a1.y), a2.y);
                        r.z = __hadd2(__hadd2(a0.z, a1.z), a2.z);
                        r.w = __hadd2(__hadd2(a0.w, a1.w), a2.w);
                        s1Q[p][i] = r;
                        s1E[p][i] = __hadd2(__hadd2(lE[p][i], lE[p][i + 1]), lE[p][i + 2]);
                    }
                }
                __syncthreads();

                // phase 2: 7-tap stride-3 stage, both pairs
                HQ sA = s1Q[0][z], sB = s1Q[1][z];
                __half2 eA = s1E[0][z], eB = s1E[1][z];
#pragma unroll
                for (int j = 3; j <= 18; j += 3) {
                    HQ vA = s1Q[0][z + j], vB = s1Q[1][z + j];
                    sA.x = __hadd2(sA.x, vA.x); sB.x = __hadd2(sB.x, vB.x);
                    sA.y = __hadd2(sA.y, vA.y); sB.y = __hadd2(sB.y, vB.y);
                    sA.z = __hadd2(sA.z, vA.z); sB.z = __hadd2(sB.z, vB.z);
                    sA.w = __hadd2(sA.w, vA.w); sB.w = __hadd2(sB.w, vB.w);
                    eA = __hadd2(eA, s1E[0][z + j]); eB = __hadd2(eB, s1E[1][z + j]);
                }

                // ring writes
                {
                    size_t rA = (ringBase + ip % RDEP) * SZ + z;
                    size_t rB = (ringBase + (ip + 1) % RDEP) * SZ + z;
                    g_rq[rA] = sA; g_re[rA] = eA;
                    g_rq[rB] = sB; g_re[rB] = eB;
                }

                // y running sums (native half), 4 lines
                c0 = __hadd(c0, __hsub(__low2half(sA.x), __high2half(hA.x)));
                c1 = __hadd(c1, __hsub(__low2half(sA.y), __high2half(hA.y)));
                c2 = __hadd(c2, __hsub(__low2half(sA.z), __high2half(hA.z)));
                c3 = __hadd(c3, __hsub(__low2half(sA.w), __high2half(hA.w)));
                c4 = __hadd(c4, __hsub(__low2half(eA),   __high2half(eA_)));
                const __half s00 = c0, s01 = c1, s02 = c2, s03 = c3, s04 = c4;
                c0 = __hadd(c0, __hsub(__high2half(sA.x), __low2half(hM.x)));
                c1 = __hadd(c1, __hsub(__high2half(sA.y), __low2half(hM.y)));
                c2 = __hadd(c2, __hsub(__high2half(sA.z), __low2half(hM.z)));
                c3 = __hadd(c3, __hsub(__high2half(sA.w), __low2half(hM.w)));
                c4 = __hadd(c4, __hsub(__high2half(eA),   __low2half(eM_)));
                const __half s10 = c0, s11 = c1, s12 = c2, s13 = c3, s14 = c4;
                c0 = __hadd(c0, __hsub(__low2half(sB.x), __high2half(hM.x)));
                c1 = __hadd(c1, __hsub(__low2half(sB.y), __high2half(hM.y)));
                c2 = __hadd(c2, __hsub(__low2half(sB.z), __high2half(hM.z)));
                c3 = __hadd(c3, __hsub(__low2half(sB.w), __high2half(hM.w)));
                c4 = __hadd(c4, __hsub(__low2half(eB),   __high2half(eM_)));
                const __half s20 = c0, s21 = c1, s22 = c2, s23 = c3, s24 = c4;
                c0 = __hadd(c0, __hsub(__high2half(sB.x), __low2half(hB.x)));
                c1 = __hadd(c1, __hsub(__high2half(sB.y), __low2half(hB.y)));
                c2 = __hadd(c2, __hsub(__high2half(sB.z), __low2half(hB.z)));
                c3 = __hadd(c3, __hsub(__high2half(sB.w), __low2half(hB.w)));
                c4 = __hadd(c4, __hsub(__high2half(eB),   __low2half(eB_)));

                // outputs: pairs (y-10, y-9) and (y-8, y-7)
                {
                    const int yo = y - HALF;
                    if (yo >= y0 && yo < y1) {
                        size_t qidx = (((size_t)(b * SX + x)) * YP + (yo >> 1)) * SZ + z;
                        HQ w;
                        w.x = __halves2half2(s00, s10);
                        w.y = __halves2half2(s01, s11);
                        w.z = __halves2half2(s02, s12);
                        w.w = __halves2half2(s03, s13);
                        g_q2[qidx] = w;
                        g_e2[qidx] = __halves2half2(s04, s14);
                    }
                }
                {
                    const int yo = y - HALF + 2;
                    if (yo >= y0 && yo < y1) {
                        size_t qidx = (((size_t)(b * SX + x)) * YP + (yo >> 1)) * SZ + z;
                        HQ w;
                        w.x = __halves2half2(s20, c0);
                        w.y = __halves2half2(s21, c1);
                        w.z = __halves2half2(s22, c2);
                        w.w = __halves2half2(s23, c3);
                        g_q2[qidx] = w;
                        g_e2[qidx] = __halves2half2(s24, c4);
                    }
                }
            }

            // publish: this tile's (b, seg) column is fully written
            __threadfence();
            __syncthreads();
            if (z == 0) atomicAdd(&g_segc[b * YSEG + seg], 1);
            __syncthreads();  // protect smem before next item
        } else {
            // ================= passC tile =================
            const int cb = item - NBLK_AB;
            const int segx = cb % XSEG;
            int t2 = cb / XSEG;
            const int yp = t2 % YP;
            const int b = t2 / YP;

            // wait until the producing segment (all SX columns) is complete
            {
                const int ysg = (2 * yp) / YL;   // rows 2yp,2yp+1 same segment
                const int idx = b * YSEG + ysg;
                if (z == 0) {
                    volatile int* p = &g_segc[idx];
                    while (*p < SX) __nanosleep(200);
                    __threadfence();
                }
                __syncthreads();
            }

            const int x0 = segx * XLEN;
            const size_t strideX = (size_t)YP * SZ;
            const size_t base = ((size_t)b * SX) * strideX + (size_t)yp * SZ + z;

            __half2 sI = zero2, sJ = zero2, sI2 = zero2, sJ2 = zero2, sIJ = zero2;
#pragma unroll
            for (int k = 0; k < WIN; k++) {
                const int xx = x0 - HALF + k;
                if (xx >= 0 && xx < SX) {
                    size_t o = base + (size_t)xx * strideX;
                    HQ h = g_q2[o];
                    __half2 e = g_e2[o];
                    sI  = __hadd2(sI,  h.x);
                    sJ  = __hadd2(sJ,  h.y);
                    sI2 = __hadd2(sI2, h.z);
                    sJ2 = __hadd2(sJ2, h.w);
                    sIJ = __hadd2(sIJ, e);
                }
            }

            const float inv_n = 1.0f / (float)(WIN * WIN * WIN);
            float acc = 0.f;

            for (int xb = 0; xb < XLEN; xb += 4) {
                HQ ha[4], hr[4];
                __half2 ea[4], er[4];
#pragma unroll
                for (int j = 0; j < 4; j++) {
                    const int xa = x0 + xb + j + HALF + 1;
                    ha[j].x = zero2; ha[j].y = zero2; ha[j].z = zero2; ha[j].w = zero2;
                    ea[j] = zero2;
                    if (xa < SX) {
                        size_t o = base + (size_t)xa * strideX;
                        ha[j] = g_q2[o]; ea[j] = g_e2[o];
                    }
                }
#pragma unroll
                for (int j = 0; j < 4; j++) {
                    const int xr = x0 + xb + j - HALF;
                    hr[j].x = zero2; hr[j].y = zero2; hr[j].z = zero2; hr[j].w = zero2;
                    er[j] = zero2;
                    if (xr >= 0) {
                        size_t o = base + (size_t)xr * strideX;
                        hr[j] = g_q2[o]; er[j] = g_e2[o];
                    }
                }
#pragma unroll
                for (int j = 0; j < 4; j++) {
                    float2 fI  = __half22float2(sI);
                    float2 fJ  = __half22float2(sJ);
                    float2 fI2 = __half22float2(sI2);
                    float2 fJ2 = __half22float2(sJ2);
                    float2 fIJ = __half22float2(sIJ);
#pragma unroll
                    for (int ln = 0; ln < 2; ln++) {
                        float t0 = ln ? fI.y : fI.x;
                        float t1 = ln ? fJ.y : fJ.x;
                        float t2c = ln ? fI2.y : fI2.x;
                        float t3 = ln ? fJ2.y : fJ2.x;
                        float t4 = ln ? fIJ.y : fIJ.x;
                        float cross = t4 - t0 * t1 * inv_n;
                        float Ivar  = t2c - t0 * t0 * inv_n;
                        float Jvar  = t3 - t1 * t1 * inv_n;
                        acc += __fdividef(cross * cross, Ivar * Jvar + 1e-5f);
                    }
                    sI  = __hadd2(sI,  __hsub2(ha[j].x, hr[j].x));
                    sJ  = __hadd2(sJ,  __hsub2(ha[j].y, hr[j].y));
                    sI2 = __hadd2(sI2, __hsub2(ha[j].z, hr[j].z));
                    sJ2 = __hadd2(sJ2, __hsub2(ha[j].w, hr[j].w));
                    sIJ = __hadd2(sIJ, __hsub2(ea[j],   er[j]));
                }
            }

            // deterministic block reduction
            float v = acc;
#pragma unroll
            for (int off = 16; off; off >>= 1)
                v += __shfl_down_sync(0xffffffffu, v, off);
            if ((threadIdx.x & 31) == 0) wsum[threadIdx.x >> 5] = v;
            __syncthreads();
            if (threadIdx.x == 0) {
                double tot = 0.0;
#pragma unroll
                for (int w = 0; w < SZ / 32; w++) tot += (double)wsum[w];
                g_part[cb] = tot;
                __threadfence();
                int n = atomicAdd(&g_count, 1);
                isLast = (n == NPART - 1);
            }
            __syncthreads();

            if (isLast) {
                double cv = 0.0;
                const int chunk = 5;             // 160*5 = 800 >= 768
                int lo = threadIdx.x * chunk;
                for (int i = lo; i < lo + chunk && i < NPART; ++i)
                    cv += g_part[i];
                shd[threadIdx.x] = cv;
                if (threadIdx.x < 256 - SZ) shd[SZ + threadIdx.x] = 0.0;
                __syncthreads();
                for (int s = 128; s; s >>= 1) {
                    if (threadIdx.x < s) shd[threadIdx.x] += shd[threadIdx.x + s];
                    __syncthreads();
                }
                if (threadIdx.x < NSEGC) g_segc[threadIdx.x] = 0;  // reset for replay
                if (threadIdx.x == 0) {
                    out[0] = (float)(1.0 - shd[0] / (double)NF);
                    g_count = 0;
                }
            }
            __syncthreads();
        }
    }
}

extern "C" void kernel_launch(void* const* d_in, const int* in_sizes, int n_in,
                              void* d_out, int out_size) {
    const float* I = (const float*)d_in[0];
    const float* J = (const float*)d_in[1];
    float* out = (float*)d_out;

    mega<<<GRID, SZ>>>(I, J, out);
}

// round 15
// speedup vs baseline: 1.1023x; 1.1023x over previous
#include <cuda_runtime.h>
#include <cuda_fp16.h>

#define SB 2
#define SX 160
#define SY 192
#define SZ 160
#define WIN 21
#define HALF 10
#define NF 9830400ull          // SB*SX*SY*SZ
#define YP (SY / 2)            // 96
#define YSEG 3
#define YL (SY / YSEG)         // 64
#define XSEG 4
#define XLEN (SX / XSEG)       // 40
#define NPART (SB * YP * XSEG) // 768
#define LPAD (SZ + 2 * HALF)   // 180
#define S1N (SZ + 18)
#define RDEP 12
#define NBLK_AB (SB * SX * YSEG)   // 960

// (I-pair, J-pair) staging: 8 bytes
struct __align__(8) H2 { __half2 x, y; };
// 4 channels packed as half2 (lane = y parity): x=(I), y=(J), z=(I2), w=(J2)
struct __align__(16) HQ { __half2 x, y, z, w; };

__device__ HQ g_q2[NF / 2];
__device__ __half2 g_e2[NF / 2];
__device__ HQ g_rq[(size_t)NBLK_AB * RDEP * SZ];
__device__ __half2 g_re[(size_t)NBLK_AB * RDEP * SZ];
__device__ double g_part[NPART];
__device__ int g_count;

// ---------------------------------------------------------------------------
// Fused pass A+B: 2 y-pairs (4 lines) per barrier set. Phase 0 stages ONLY
// (I,J) pairs (8 B); phase 1 forms the products on the fly (9 HMUL2/pair)
// while computing the 3-tap sums -> 20% less smem-crossbar traffic.
// Phase 2 = 7-tap stride-3 stage. y-filter = native-half running sums with a
// GMEM pair-ring (3 prefetched subtrahends). Identical arithmetic to the
// previous version (same fp16 values, multiplied later).
// ---------------------------------------------------------------------------
__global__ __launch_bounds__(SZ, 6) void passAB(const float* __restrict__ I,
                                                const float* __restrict__ J) {
    __shared__ H2      lQ[2][LPAD];
    __shared__ HQ      s1Q[2][S1N];
    __shared__ __half2 s1E[2][S1N];

    const int z = threadIdx.x;
    int bid = blockIdx.x;
    const int seg = bid % YSEG;
    int t = bid / YSEG;
    const int x = t % SX;
    const int b = t / SX;

    const __half2 zero2 = __floats2half2_rn(0.f, 0.f);
    const __half zeroh = __float2half(0.f);

    if (z < HALF) {
        H2 z2; z2.x = zero2; z2.y = zero2;
#pragma unroll
        for (int p = 0; p < 2; p++) {
            lQ[p][z] = z2; lQ[p][SZ + HALF + z] = z2;
        }
    }

    const int y0 = seg * YL;
    const int y1 = y0 + YL;
    const int ystart = (y0 - HALF > 0) ? (y0 - HALF) : 0;  // even
    const size_t planeBase = ((size_t)(b * SX + x)) * SY * SZ;
    const size_t ringBase = (size_t)bid * RDEP;

    __half c0 = zeroh, c1 = zeroh, c2 = zeroh, c3 = zeroh, c4 = zeroh;

    float pi[4], pj[4];
#pragma unroll
    for (int l = 0; l < 4; l++) {
        pi[l] = 0.f; pj[l] = 0.f;
        const int yy = ystart + l;
        if (yy < SY) {
            size_t o = planeBase + (size_t)yy * SZ + z;
            pi[l] = I[o]; pj[l] = J[o];
        }
    }

    __syncthreads();

    for (int y = ystart; y < y1 + HALF; y += 4) {
        const int ip = (y - ystart) >> 1;

        // ---- ring prefetch: pairs ip-11, ip-10, ip-9 (consume after ph2) ----
        HQ hA, hM, hB; __half2 eA_, eM_, eB_;
        hA.x = zero2; hA.y = zero2; hA.z = zero2; hA.w = zero2; eA_ = zero2;
        hM = hA; eM_ = zero2; hB = hA; eB_ = zero2;
        if (ip >= 11) {
            size_t r = (ringBase + (ip - 11) % RDEP) * SZ + z;
            hA = g_rq[r]; eA_ = g_re[r];
        }
        if (ip >= 10) {
            size_t r = (ringBase + (ip - 10) % RDEP) * SZ + z;
            hM = g_rq[r]; eM_ = g_re[r];
        }
        if (ip >= 9) {
            size_t r = (ringBase + (ip - 9) % RDEP) * SZ + z;
            hB = g_rq[r]; eB_ = g_re[r];
        }

        // ---- phase 0: stage (I,J) pairs only ----
#pragma unroll
        for (int p = 0; p < 2; p++) {
            H2 h;
            h.x = __floats2half2_rn(pi[2 * p], pi[2 * p + 1]);
            h.y = __floats2half2_rn(pj[2 * p], pj[2 * p + 1]);
            lQ[p][HALF + z] = h;
        }

        // ---- prefetch next 4 lines ----
#pragma unroll
        for (int l = 0; l < 4; l++) {
            pi[l] = 0.f; pj[l] = 0.f;
            const int yn = y + 4 + l;
            if (yn < SY) {
                size_t o = planeBase + (size_t)yn * SZ + z;
                pi[l] = I[o]; pj[l] = J[o];
            }
        }
        __syncthreads();

        // ---- phase 1: 3-tap stage with on-the-fly products ----
#pragma unroll
        for (int p = 0; p < 2; p++) {
            {
                const int i = z;
                H2 a0 = lQ[p][i], a1 = lQ[p][i + 1], a2 = lQ[p][i + 2];
                HQ r;
                r.x = __hadd2(__hadd2(a0.x, a1.x), a2.x);
                r.y = __hadd2(__hadd2(a0.y, a1.y), a2.y);
                r.z = __hadd2(__hadd2(__hmul2(a0.x, a0.x), __hmul2(a1.x, a1.x)),
                              __hmul2(a2.x, a2.x));
                r.w = __hadd2(__hadd2(__hmul2(a0.y, a0.y), __hmul2(a1.y, a1.y)),
                              __hmul2(a2.y, a2.y));
                s1Q[p][i] = r;
                s1E[p][i] = __hadd2(__hadd2(__hmul2(a0.x, a0.y), __hmul2(a1.x, a1.y)),
                                    __hmul2(a2.x, a2.y));
            }
            if (z < S1N - SZ) {
                const int i = SZ + z;
                H2 a0 = lQ[p][i], a1 = lQ[p][i + 1], a2 = lQ[p][i + 2];
                HQ r;
                r.x = __hadd2(__hadd2(a0.x, a1.x), a2.x);
                r.y = __hadd2(__hadd2(a0.y, a1.y), a2.y);
                r.z = __hadd2(__hadd2(__hmul2(a0.x, a0.x), __hmul2(a1.x, a1.x)),
                              __hmul2(a2.x, a2.x));
                r.w = __hadd2(__hadd2(__hmul2(a0.y, a0.y), __hmul2(a1.y, a1.y)),
                              __hmul2(a2.y, a2.y));
                s1Q[p][i] = r;
                s1E[p][i] = __hadd2(__hadd2(__hmul2(a0.x, a0.y), __hmul2(a1.x, a1.y)),
                                    __hmul2(a2.x, a2.y));
            }
        }
        __syncthreads();

        // ---- phase 2: 7-tap stride-3 stage, both pairs interleaved ----
        HQ sA = s1Q[0][z], sB = s1Q[1][z];
        __half2 eA = s1E[0][z], eB = s1E[1][z];
#pragma unroll
        for (int j = 3; j <= 18; j += 3) {
            HQ vA = s1Q[0][z + j], vB = s1Q[1][z + j];
            sA.x = __hadd2(sA.x, vA.x); sB.x = __hadd2(sB.x, vB.x);
            sA.y = __hadd2(sA.y, vA.y); sB.y = __hadd2(sB.y, vB.y);
            sA.z = __hadd2(sA.z, vA.z); sB.z = __hadd2(sB.z, vB.z);
            sA.w = __hadd2(sA.w, vA.w); sB.w = __hadd2(sB.w, vB.w);
            eA = __hadd2(eA, s1E[0][z + j]); eB = __hadd2(eB, s1E[1][z + j]);
        }

        // ---- ring writes (reads already prefetched) ----
        {
            size_t rA = (ringBase + ip % RDEP) * SZ + z;
            size_t rB = (ringBase + (ip + 1) % RDEP) * SZ + z;
            g_rq[rA] = sA; g_re[rA] = eA;
            g_rq[rB] = sB; g_re[rB] = eB;
        }

        // ---- y running sums (native half), 4 lines in order ----
        c0 = __hadd(c0, __hsub(__low2half(sA.x), __high2half(hA.x)));
        c1 = __hadd(c1, __hsub(__low2half(sA.y), __high2half(hA.y)));
        c2 = __hadd(c2, __hsub(__low2half(sA.z), __high2half(hA.z)));
        c3 = __hadd(c3, __hsub(__low2half(sA.w), __high2half(hA.w)));
        c4 = __hadd(c4, __hsub(__low2half(eA),   __high2half(eA_)));
        const __half s00 = c0, s01 = c1, s02 = c2, s03 = c3, s04 = c4;
        c0 = __hadd(c0, __hsub(__high2half(sA.x), __low2half(hM.x)));
        c1 = __hadd(c1, __hsub(__high2half(sA.y), __low2half(hM.y)));
        c2 = __hadd(c2, __hsub(__high2half(sA.z), __low2half(hM.z)));
        c3 = __hadd(c3, __hsub(__high2half(sA.w), __low2half(hM.w)));
        c4 = __hadd(c4, __hsub(__high2half(eA),   __low2half(eM_)));
        const __half s10 = c0, s11 = c1, s12 = c2, s13 = c3, s14 = c4;
        c0 = __hadd(c0, __hsub(__low2half(sB.x), __high2half(hM.x)));
        c1 = __hadd(c1, __hsub(__low2half(sB.y), __high2half(hM.y)));
        c2 = __hadd(c2, __hsub(__low2half(sB.z), __high2half(hM.z)));
        c3 = __hadd(c3, __hsub(__low2half(sB.w), __high2half(hM.w)));
        c4 = __hadd(c4, __hsub(__low2half(eB),   __high2half(eM_)));
        const __half s20 = c0, s21 = c1, s22 = c2, s23 = c3, s24 = c4;
        c0 = __hadd(c0, __hsub(__high2half(sB.x), __low2half(hB.x)));
        c1 = __hadd(c1, __hsub(__high2half(sB.y), __low2half(hB.y)));
        c2 = __hadd(c2, __hsub(__high2half(sB.z), __low2half(hB.z)));
        c3 = __hadd(c3, __hsub(__high2half(sB.w), __low2half(hB.w)));
        c4 = __hadd(c4, __hsub(__high2half(eB),   __low2half(eB_)));

        // ---- outputs: pairs (y-10, y-9) and (y-8, y-7) ----
        {
            const int yo = y - HALF;
            if (yo >= y0 && yo < y1) {
                size_t qidx = (((size_t)(b * SX + x)) * YP + (yo >> 1)) * SZ + z;
                HQ w;
                w.x = __halves2half2(s00, s10);
                w.y = __halves2half2(s01, s11);
                w.z = __halves2half2(s02, s12);
                w.w = __halves2half2(s03, s13);
                g_q2[qidx] = w;
                g_e2[qidx] = __halves2half2(s04, s14);
            }
        }
        {
            const int yo = y - HALF + 2;
            if (yo >= y0 && yo < y1) {
                size_t qidx = (((size_t)(b * SX + x)) * YP + (yo >> 1)) * SZ + z;
                HQ w;
                w.x = __halves2half2(s20, c0);
                w.y = __halves2half2(s21, c1);
                w.z = __halves2half2(s22, c2);
                w.w = __halves2half2(s23, c3);
                g_q2[qidx] = w;
                g_e2[qidx] = __halves2half2(s24, c4);
            }
        }
    }
}

// ---------------------------------------------------------------------------
// Pass C: x box filter over y-pair-packed data. Window sums in native half2;
// fp32 only at cc. Fast divide. Unroll-4, batched loads (MLP 8).
// Deterministic partials; last block does a fixed-order final reduction.
// ---------------------------------------------------------------------------
__global__ __launch_bounds__(SZ, 6) void passC(float* __restrict__ out) {
    int bid = blockIdx.x;
    const int seg = bid % XSEG;
    int t = bid / XSEG;
    const int yp = t % YP;
    const int b = t / YP;
    const int z = threadIdx.x;

    const int x0 = seg * XLEN;
    const size_t strideX = (size_t)YP * SZ;
    const size_t base = ((size_t)b * SX) * strideX + (size_t)yp * SZ + z;

    const __half2 zero2 = __floats2half2_rn(0.f, 0.f);
    __half2 sI = zero2, sJ = zero2, sI2 = zero2, sJ2 = zero2, sIJ = zero2;

#pragma unroll
    for (int k = 0; k < WIN; k++) {
        const int xx = x0 - HALF + k;
        if (xx >= 0 && xx < SX) {
            size_t o = base + (size_t)xx * strideX;
            HQ h = g_q2[o];
            __half2 e = g_e2[o];
            sI  = __hadd2(sI,  h.x);
            sJ  = __hadd2(sJ,  h.y);
            sI2 = __hadd2(sI2, h.z);
            sJ2 = __hadd2(sJ2, h.w);
            sIJ = __hadd2(sIJ, e);
        }
    }

    const float inv_n = 1.0f / (float)(WIN * WIN * WIN);
    float acc = 0.f;

    for (int xb = 0; xb < XLEN; xb += 4) {
        HQ ha[4], hr[4];
        __half2 ea[4], er[4];
#pragma unroll
        for (int j = 0; j < 4; j++) {
            const int xa = x0 + xb + j + HALF + 1;
            ha[j].x = zero2; ha[j].y = zero2; ha[j].z = zero2; ha[j].w = zero2;
            ea[j] = zero2;
            if (xa < SX) {
                size_t o = base + (size_t)xa * strideX;
                ha[j] = g_q2[o]; ea[j] = g_e2[o];
            }
        }
#pragma unroll
        for (int j = 0; j < 4; j++) {
            const int xr = x0 + xb + j - HALF;
            hr[j].x = zero2; hr[j].y = zero2; hr[j].z = zero2; hr[j].w = zero2;
            er[j] = zero2;
            if (xr >= 0) {
                size_t o = base + (size_t)xr * strideX;
                hr[j] = g_q2[o]; er[j] = g_e2[o];
            }
        }
#pragma unroll
        for (int j = 0; j < 4; j++) {
            float2 fI  = __half22float2(sI);
            float2 fJ  = __half22float2(sJ);
            float2 fI2 = __half22float2(sI2);
            float2 fJ2 = __half22float2(sJ2);
            float2 fIJ = __half22float2(sIJ);
#pragma unroll
            for (int ln = 0; ln < 2; ln++) {
                float t0 = ln ? fI.y : fI.x;
                float t1 = ln ? fJ.y : fJ.x;
                float t2 = ln ? fI2.y : fI2.x;
                float t3 = ln ? fJ2.y : fJ2.x;
                float t4 = ln ? fIJ.y : fIJ.x;
                float cross = t4 - t0 * t1 * inv_n;
                float Ivar  = t2 - t0 * t0 * inv_n;
                float Jvar  = t3 - t1 * t1 * inv_n;
                acc += __fdividef(cross * cross, Ivar * Jvar + 1e-5f);
            }
            sI  = __hadd2(sI,  __hsub2(ha[j].x, hr[j].x));
            sJ  = __hadd2(sJ,  __hsub2(ha[j].y, hr[j].y));
            sI2 = __hadd2(sI2, __hsub2(ha[j].z, hr[j].z));
            sJ2 = __hadd2(sJ2, __hsub2(ha[j].w, hr[j].w));
            sIJ = __hadd2(sIJ, __hsub2(ea[j],   er[j]));
        }
    }

    // deterministic block reduction (160 threads = 5 warps)
    __shared__ float wsum[SZ / 32];
    __shared__ int isLast;
    float v = acc;
#pragma unroll
    for (int off = 16; off; off >>= 1)
        v += __shfl_down_sync(0xffffffffu, v, off);
    if ((threadIdx.x & 31) == 0) wsum[threadIdx.x >> 5] = v;
    __syncthreads();
    if (threadIdx.x == 0) {
        double tot = 0.0;
#pragma unroll
        for (int w = 0; w < SZ / 32; w++) tot += (double)wsum[w];
        g_part[bid] = tot;
        __threadfence();
        int n = atomicAdd(&g_count, 1);
        isLast = (n == NPART - 1);
    }
    __syncthreads();

    if (isLast) {
        __shared__ double sh[256];
        double cv = 0.0;
        const int chunk = 5;                 // 160 * 5 = 800 >= 768
        int lo = threadIdx.x * chunk;
        for (int i = lo; i < lo + chunk && i < NPART; ++i)
            cv += g_part[i];
        sh[threadIdx.x] = cv;
        if (threadIdx.x < 256 - SZ) sh[SZ + threadIdx.x] = 0.0;
        __syncthreads();
        for (int s = 128; s; s >>= 1) {
            if (threadIdx.x < s) sh[threadIdx.x] += sh[threadIdx.x + s];
            __syncthreads();
        }
        if (threadIdx.x == 0) {
            out[0] = (float)(1.0 - sh[0] / (double)NF);
            g_count = 0;                      // reset for next graph replay
        }
    }
}

extern "C" void kernel_launch(void* const* d_in, const int* in_sizes, int n_in,
                              void* d_out, int out_size) {
    const float* I = (const float*)d_in[0];
    const float* J = (const float*)d_in[1];
    float* out = (float*)d_out;

    passAB<<<NBLK_AB, SZ>>>(I, J);
    passC<<<NPART, SZ>>>(out);
}

// round 16
// speedup vs baseline: 1.1283x; 1.0236x over previous
#include <cuda_runtime.h>
#include <cuda_fp16.h>

#define SB 2
#define SX 160
#define SY 192
#define SZ 160
#define WIN 21
#define HALF 10
#define NF 9830400ull          // SB*SX*SY*SZ
#define YP (SY / 2)            // 96
#define YSEG 3
#define YL (SY / YSEG)         // 64
#define XSEG 4
#define XLEN (SX / XSEG)       // 40
#define NPART (SB * YP * XSEG) // 768
#define LPAD (SZ + 2 * HALF)   // 180
#define S1N (SZ + 14)          // stage1 (7-tap) output range: 174
#define RDEP 12
#define NBLK_AB (SB * SX * YSEG)   // 960

// (I-pair, J-pair) staging: 8 bytes
struct __align__(8) H2 { __half2 x, y; };
// 4 channels packed as half2 (lane = y parity): x=(I), y=(J), z=(I2), w=(J2)
struct __align__(16) HQ { __half2 x, y, z, w; };

__device__ HQ g_q2[NF / 2];
__device__ __half2 g_e2[NF / 2];
__device__ HQ g_rq[(size_t)NBLK_AB * RDEP * SZ];
__device__ __half2 g_re[(size_t)NBLK_AB * RDEP * SZ];
__device__ double g_part[NPART];
__device__ int g_count;

// ---------------------------------------------------------------------------
// Fused pass A+B: 2 y-pairs (4 lines) per barrier set.
// z-filter factorization REVERSED vs before: stage 1 = 7-tap over the 8-byte
// (I,J) staging with products formed on the fly; stage 2 = 3-tap stride-7
// over the 20-byte 5-channel records. Crossbar bytes/pair: 192 -> 151.
// y-filter = native-half running sums with a GMEM pair-ring (3 prefetched
// subtrahends consumed after phase 2).
// ---------------------------------------------------------------------------
__global__ __launch_bounds__(SZ, 6) void passAB(const float* __restrict__ I,
                                                const float* __restrict__ J) {
    __shared__ H2      lQ[2][LPAD];
    __shared__ HQ      s1Q[2][S1N];
    __shared__ __half2 s1E[2][S1N];

    const int z = threadIdx.x;
    int bid = blockIdx.x;
    const int seg = bid % YSEG;
    int t = bid / YSEG;
    const int x = t % SX;
    const int b = t / SX;

    const __half2 zero2 = __floats2half2_rn(0.f, 0.f);
    const __half zeroh = __float2half(0.f);

    if (z < HALF) {
        H2 z2; z2.x = zero2; z2.y = zero2;
#pragma unroll
        for (int p = 0; p < 2; p++) {
            lQ[p][z] = z2; lQ[p][SZ + HALF + z] = z2;
        }
    }

    const int y0 = seg * YL;
    const int y1 = y0 + YL;
    const int ystart = (y0 - HALF > 0) ? (y0 - HALF) : 0;  // even
    const size_t planeBase = ((size_t)(b * SX + x)) * SY * SZ;
    const size_t ringBase = (size_t)bid * RDEP;

    __half c0 = zeroh, c1 = zeroh, c2 = zeroh, c3 = zeroh, c4 = zeroh;

    float pi[4], pj[4];
#pragma unroll
    for (int l = 0; l < 4; l++) {
        pi[l] = 0.f; pj[l] = 0.f;
        const int yy = ystart + l;
        if (yy < SY) {
            size_t o = planeBase + (size_t)yy * SZ + z;
            pi[l] = I[o]; pj[l] = J[o];
        }
    }

    __syncthreads();

    for (int y = ystart; y < y1 + HALF; y += 4) {
        const int ip = (y - ystart) >> 1;

        // ---- ring prefetch: pairs ip-11, ip-10, ip-9 (consume after ph2) ----
        HQ hA, hM, hB; __half2 eA_, eM_, eB_;
        hA.x = zero2; hA.y = zero2; hA.z = zero2; hA.w = zero2; eA_ = zero2;
        hM = hA; eM_ = zero2; hB = hA; eB_ = zero2;
        if (ip >= 11) {
            size_t r = (ringBase + (ip - 11) % RDEP) * SZ + z;
            hA = g_rq[r]; eA_ = g_re[r];
        }
        if (ip >= 10) {
            size_t r = (ringBase + (ip - 10) % RDEP) * SZ + z;
            hM = g_rq[r]; eM_ = g_re[r];
        }
        if (ip >= 9) {
            size_t r = (ringBase + (ip - 9) % RDEP) * SZ + z;
            hB = g_rq[r]; eB_ = g_re[r];
        }

        // ---- phase 0: stage (I,J) pairs only ----
#pragma unroll
        for (int p = 0; p < 2; p++) {
            H2 h;
            h.x = __floats2half2_rn(pi[2 * p], pi[2 * p + 1]);
            h.y = __floats2half2_rn(pj[2 * p], pj[2 * p + 1]);
            lQ[p][HALF + z] = h;
        }

        // ---- prefetch next 4 lines ----
#pragma unroll
        for (int l = 0; l < 4; l++) {
            pi[l] = 0.f; pj[l] = 0.f;
            const int yn = y + 4 + l;
            if (yn < SY) {
                size_t o = planeBase + (size_t)yn * SZ + z;
                pi[l] = I[o]; pj[l] = J[o];
            }
        }
        __syncthreads();

        // ---- phase 1: 7-tap stage with on-the-fly products ----
#pragma unroll
        for (int p = 0; p < 2; p++) {
            {
                const int i = z;
                H2 a0 = lQ[p][i];
                __half2 sx = a0.x, sy = a0.y;
                __half2 sxx = __hmul2(a0.x, a0.x);
                __half2 syy = __hmul2(a0.y, a0.y);
                __half2 sxy = __hmul2(a0.x, a0.y);
#pragma unroll
                for (int k = 1; k < 7; k++) {
                    H2 a = lQ[p][i + k];
                    sx = __hadd2(sx, a.x);
                    sy = __hadd2(sy, a.y);
                    sxx = __hadd2(sxx, __hmul2(a.x, a.x));
                    syy = __hadd2(syy, __hmul2(a.y, a.y));
                    sxy = __hadd2(sxy, __hmul2(a.x, a.y));
                }
                HQ r; r.x = sx; r.y = sy; r.z = sxx; r.w = syy;
                s1Q[p][i] = r;
                s1E[p][i] = sxy;
            }
            if (z < S1N - SZ) {
                const int i = SZ + z;
                H2 a0 = lQ[p][i];
                __half2 sx = a0.x, sy = a0.y;
                __half2 sxx = __hmul2(a0.x, a0.x);
                __half2 syy = __hmul2(a0.y, a0.y);
                __half2 sxy = __hmul2(a0.x, a0.y);
#pragma unroll
                for (int k = 1; k < 7; k++) {
                    H2 a = lQ[p][i + k];
                    sx = __hadd2(sx, a.x);
                    sy = __hadd2(sy, a.y);
                    sxx = __hadd2(sxx, __hmul2(a.x, a.x));
                    syy = __hadd2(syy, __hmul2(a.y, a.y));
                    sxy = __hadd2(sxy, __hmul2(a.x, a.y));
                }
                HQ r; r.x = sx; r.y = sy; r.z = sxx; r.w = syy;
                s1Q[p][i] = r;
                s1E[p][i] = sxy;
            }
        }
        __syncthreads();

        // ---- phase 2: 3-tap stride-7 stage, both pairs interleaved ----
        HQ sA = s1Q[0][z], sB = s1Q[1][z];
        __half2 eA = s1E[0][z], eB = s1E[1][z];
#pragma unroll
        for (int j = 7; j <= 14; j += 7) {
            HQ vA = s1Q[0][z + j], vB = s1Q[1][z + j];
            sA.x = __hadd2(sA.x, vA.x); sB.x = __hadd2(sB.x, vB.x);
            sA.y = __hadd2(sA.y, vA.y); sB.y = __hadd2(sB.y, vB.y);
            sA.z = __hadd2(sA.z, vA.z); sB.z = __hadd2(sB.z, vB.z);
            sA.w = __hadd2(sA.w, vA.w); sB.w = __hadd2(sB.w, vB.w);
            eA = __hadd2(eA, s1E[0][z + j]); eB = __hadd2(eB, s1E[1][z + j]);
        }

        // ---- ring writes (reads already prefetched) ----
        {
            size_t rA = (ringBase + ip % RDEP) * SZ + z;
            size_t rB = (ringBase + (ip + 1) % RDEP) * SZ + z;
            g_rq[rA] = sA; g_re[rA] = eA;
            g_rq[rB] = sB; g_re[rB] = eB;
        }

        // ---- y running sums (native half), 4 lines in order ----
        c0 = __hadd(c0, __hsub(__low2half(sA.x), __high2half(hA.x)));
        c1 = __hadd(c1, __hsub(__low2half(sA.y), __high2half(hA.y)));
        c2 = __hadd(c2, __hsub(__low2half(sA.z), __high2half(hA.z)));
        c3 = __hadd(c3, __hsub(__low2half(sA.w), __high2half(hA.w)));
        c4 = __hadd(c4, __hsub(__low2half(eA),   __high2half(eA_)));
        const __half s00 = c0, s01 = c1, s02 = c2, s03 = c3, s04 = c4;
        c0 = __hadd(c0, __hsub(__high2half(sA.x), __low2half(hM.x)));
        c1 = __hadd(c1, __hsub(__high2half(sA.y), __low2half(hM.y)));
        c2 = __hadd(c2, __hsub(__high2half(sA.z), __low2half(hM.z)));
        c3 = __hadd(c3, __hsub(__high2half(sA.w), __low2half(hM.w)));
        c4 = __hadd(c4, __hsub(__high2half(eA),   __low2half(eM_)));
        const __half s10 = c0, s11 = c1, s12 = c2, s13 = c3, s14 = c4;
        c0 = __hadd(c0, __hsub(__low2half(sB.x), __high2half(hM.x)));
        c1 = __hadd(c1, __hsub(__low2half(sB.y), __high2half(hM.y)));
        c2 = __hadd(c2, __hsub(__low2half(sB.z), __high2half(hM.z)));
        c3 = __hadd(c3, __hsub(__low2half(sB.w), __high2half(hM.w)));
        c4 = __hadd(c4, __hsub(__low2half(eB),   __high2half(eM_)));
        const __half s20 = c0, s21 = c1, s22 = c2, s23 = c3, s24 = c4;
        c0 = __hadd(c0, __hsub(__high2half(sB.x), __low2half(hB.x)));
        c1 = __hadd(c1, __hsub(__high2half(sB.y), __low2half(hB.y)));
        c2 = __hadd(c2, __hsub(__high2half(sB.z), __low2half(hB.z)));
        c3 = __hadd(c3, __hsub(__high2half(sB.w), __low2half(hB.w)));
        c4 = __hadd(c4, __hsub(__high2half(eB),   __low2half(eB_)));

        // ---- outputs: pairs (y-10, y-9) and (y-8, y-7) ----
        {
            const int yo = y - HALF;
            if (yo >= y0 && yo < y1) {
                size_t qidx = (((size_t)(b * SX + x)) * YP + (yo >> 1)) * SZ + z;
                HQ w;
                w.x = __halves2half2(s00, s10);
                w.y = __halves2half2(s01, s11);
                w.z = __halves2half2(s02, s12);
                w.w = __halves2half2(s03, s13);
                g_q2[qidx] = w;
                g_e2[qidx] = __halves2half2(s04, s14);
            }
        }
        {
            const int yo = y - HALF + 2;
            if (yo >= y0 && yo < y1) {
                size_t qidx = (((size_t)(b * SX + x)) * YP + (yo >> 1)) * SZ + z;
                HQ w;
                w.x = __halves2half2(s20, c0);
                w.y = __halves2half2(s21, c1);
                w.z = __halves2half2(s22, c2);
                w.w = __halves2half2(s23, c3);
                g_q2[qidx] = w;
                g_e2[qidx] = __halves2half2(s24, c4);
            }
        }
    }
}

// ---------------------------------------------------------------------------
// Pass C: x box filter over y-pair-packed data. Window sums in native half2;
// fp32 only at cc. Fast divide. Unroll-4, batched loads (MLP 8).
// Deterministic partials; last block does a fixed-order final reduction.
// ---------------------------------------------------------------------------
__global__ __launch_bounds__(SZ, 6) void passC(float* __restrict__ out) {
    int bid = blockIdx.x;
    const int seg = bid % XSEG;
    int t = bid / XSEG;
    const int yp = t % YP;
    const int b = t / YP;
    const int z = threadIdx.x;

    const int x0 = seg * XLEN;
    const size_t strideX = (size_t)YP * SZ;
    const size_t base = ((size_t)b * SX) * strideX + (size_t)yp * SZ + z;

    const __half2 zero2 = __floats2half2_rn(0.f, 0.f);
    __half2 sI = zero2, sJ = zero2, sI2 = zero2, sJ2 = zero2, sIJ = zero2;

#pragma unroll
    for (int k = 0; k < WIN; k++) {
        const int xx = x0 - HALF + k;
        if (xx >= 0 && xx < SX) {
            size_t o = base + (size_t)xx * strideX;
            HQ h = g_q2[o];
            __half2 e = g_e2[o];
            sI  = __hadd2(sI,  h.x);
            sJ  = __hadd2(sJ,  h.y);
            sI2 = __hadd2(sI2, h.z);
            sJ2 = __hadd2(sJ2, h.w);
            sIJ = __hadd2(sIJ, e);
        }
    }

    const float inv_n = 1.0f / (float)(WIN * WIN * WIN);
    float acc = 0.f;

    for (int xb = 0; xb < XLEN; xb += 4) {
        HQ ha[4], hr[4];
        __half2 ea[4], er[4];
#pragma unroll
        for (int j = 0; j < 4; j++) {
            const int xa = x0 + xb + j + HALF + 1;
            ha[j].x = zero2; ha[j].y = zero2; ha[j].z = zero2; ha[j].w = zero2;
            ea[j] = zero2;
            if (xa < SX) {
                size_t o = base + (size_t)xa * strideX;
                ha[j] = g_q2[o]; ea[j] = g_e2[o];
            }
        }
#pragma unroll
        for (int j = 0; j < 4; j++) {
            const int xr = x0 + xb + j - HALF;
            hr[j].x = zero2; hr[j].y = zero2; hr[j].z = zero2; hr[j].w = zero2;
            er[j] = zero2;
            if (xr >= 0) {
                size_t o = base + (size_t)xr * strideX;
                hr[j] = g_q2[o]; er[j] = g_e2[o];
            }
        }
#pragma unroll
        for (int j = 0; j < 4; j++) {
            float2 fI  = __half22float2(sI);
            float2 fJ  = __half22float2(sJ);
            float2 fI2 = __half22float2(sI2);
            float2 fJ2 = __half22float2(sJ2);
            float2 fIJ = __half22float2(sIJ);
#pragma unroll
            for (int ln = 0; ln < 2; ln++) {
                float t0 = ln ? fI.y : fI.x;
                float t1 = ln ? fJ.y : fJ.x;
                float t2 = ln ? fI2.y : fI2.x;
                float t3 = ln ? fJ2.y : fJ2.x;
                float t4 = ln ? fIJ.y : fIJ.x;
                float cross = t4 - t0 * t1 * inv_n;
                float Ivar  = t2 - t0 * t0 * inv_n;
                float Jvar  = t3 - t1 * t1 * inv_n;
                acc += __fdividef(cross * cross, Ivar * Jvar + 1e-5f);
            }
            sI  = __hadd2(sI,  __hsub2(ha[j].x, hr[j].x));
            sJ  = __hadd2(sJ,  __hsub2(ha[j].y, hr[j].y));
            sI2 = __hadd2(sI2, __hsub2(ha[j].z, hr[j].z));
            sJ2 = __hadd2(sJ2, __hsub2(ha[j].w, hr[j].w));
            sIJ = __hadd2(sIJ, __hsub2(ea[j],   er[j]));
        }
    }

    // deterministic block reduction (160 threads = 5 warps)
    __shared__ float wsum[SZ / 32];
    __shared__ int isLast;
    float v = acc;
#pragma unroll
    for (int off = 16; off; off >>= 1)
        v += __shfl_down_sync(0xffffffffu, v, off);
    if ((threadIdx.x & 31) == 0) wsum[threadIdx.x >> 5] = v;
    __syncthreads();
    if (threadIdx.x == 0) {
        double tot = 0.0;
#pragma unroll
        for (int w = 0; w < SZ / 32; w++) tot += (double)wsum[w];
        g_part[bid] = tot;
        __threadfence();
        int n = atomicAdd(&g_count, 1);
        isLast = (n == NPART - 1);
    }
    __syncthreads();

    if (isLast) {
        __shared__ double sh[256];
        double cv = 0.0;
        const int chunk = 5;                 // 160 * 5 = 800 >= 768
        int lo = threadIdx.x * chunk;
        for (int i = lo; i < lo + chunk && i < NPART; ++i)
            cv += g_part[i];
        sh[threadIdx.x] = cv;
        if (threadIdx.x < 256 - SZ) sh[SZ + threadIdx.x] = 0.0;
        __syncthreads();
        for (int s = 128; s; s >>= 1) {
            if (threadIdx.x < s) sh[threadIdx.x] += sh[threadIdx.x + s];
            __syncthreads();
        }
        if (threadIdx.x == 0) {
            out[0] = (float)(1.0 - sh[0] / (double)NF);
            g_count = 0;                      // reset for next graph replay
        }
    }
}

extern "C" void kernel_launch(void* const* d_in, const int* in_sizes, int n_in,
                              void* d_out, int out_size) {
    const float* I = (const float*)d_in[0];
    const float* J = (const float*)d_in[1];
    float* out = (float*)d_out;

    passAB<<<NBLK_AB, SZ>>>(I, J);
    passC<<<NPART, SZ>>>(out);
}